// round 14
// baseline (speedup 1.0000x reference)
#include <cuda_runtime.h>
#include <cstdint>

// Problem constants (fixed shapes from reference_code)
#define BB 8
#define CC 128
#define LL 16384
#define KW 7
#define STR 3
#define PDD 3
#define IC 64
#define CKD (CC * KW)                   // 896
#define LPAD (LL + 2 * PDD)             // 16390
#define PP ((LPAD - KW) / STR + 1)      // 5462
#define MP 5464                         // XPK stream length (windows, padded, 16B-mult)
#define SEG 1024                        // de-interleave segment (windows per block)

using u64 = unsigned long long;

// Scratch (allocation-free rule: __device__ globals). __align__(16): all hot
// accesses are float4/ulonglong2; strides are 16B-multiples, base is the hazard.
__device__ __align__(16) float g_W1T[CKD * IC];                   // W1 transposed: [ck][o]
__device__ __align__(16) float g_W2P[16 * IC * 64];               // W2 packed: [cg][jj][ch*8+k], col7 pad=0
__device__ __align__(16) float g_XPK[(size_t)BB * CKD * MP + 64]; // [b][ck][m] = xp[b][ck/7][3m + ck%7]

__device__ __forceinline__ u64 pack2(float lo, float hi) {
    u64 r; asm("mov.b64 %0, {%1, %2};" : "=l"(r) : "f"(lo), "f"(hi)); return r;
}
__device__ __forceinline__ void unpack2(u64 v, float &lo, float &hi) {
    asm("mov.b64 {%0, %1}, %2;" : "=f"(lo), "=f"(hi) : "l"(v));
}
// Packed dual-FP32 FMA (FFMA2) — 2 fp32 FMA per issue slot on sm_103a (PTX-only form).
__device__ __forceinline__ void ffma2(u64 &d, u64 a, u64 b) {
    asm("fma.rn.f32x2 %0, %1, %2, %0;" : "+l"(d) : "l"(a), "l"(b));
}

// ---------------------------------------------------------------------------
// Prep A (merged): transpose W1 [64][896] -> [896][64]  AND  pack W2 into the
// exact smem layout phase 2 consumes:
//   g_W2P[cg*4096 + jj*64 + ch*8 + k] = W2[((cg*8+ch)*7 + k)*64 + jj]; k==7 -> 0
// One launch instead of two.
// ---------------------------------------------------------------------------
#define W1T_N (IC * CKD)        // 57344
#define W2P_N (16 * IC * 64)    // 65536

__global__ void k_prep_weights(const float* __restrict__ W1,
                               const float* __restrict__ W2) {
    int idx = blockIdx.x * 256 + threadIdx.x;
    if (idx < W1T_N) {
        int o = idx / CKD;
        int ck = idx - o * CKD;
        g_W1T[ck * IC + o] = W1[idx];
    } else if (idx < W1T_N + W2P_N) {
        int i2  = idx - W1T_N;
        int cg  = i2 >> 12;
        int rem = i2 & 4095;
        int jj  = rem >> 6;
        int col = rem & 63;
        int ch  = col >> 3;
        int k   = col & 7;
        g_W2P[i2] = (k == KW) ? 0.f
                  : __ldg(W2 + (size_t)((cg * 8 + ch) * KW + k) * IC + jj);
    }
}

// ---------------------------------------------------------------------------
// Prep B: de-interleave x by conv phase.
//   XPK[b][c*7+k][m] = xp[b][c][3m+k] = x[b][c][(3m+k-3) mod L]
// Patch rows contiguous in m -> fused kernel's B-fill is pure float4.
// Store side vectorized: each thread emits one aligned STG.128 per tap
// (MP, m0, v0 all mult of 4 -> no guard straddle).
// ---------------------------------------------------------------------------
__global__ void __launch_bounds__(256) k_deinterleave(const float* __restrict__ x) {
    __shared__ float s[3 * SEG + 8];
    const int b = blockIdx.z, c = blockIdx.y, seg = blockIdx.x;
    const int m0 = seg * SEG;
    const float* xc = x + ((size_t)b * CC + c) * LL;

    for (int u = threadIdx.x; u < 3 * SEG + 6; u += 256) {
        int j = 3 * m0 + u - PDD;
        if (j < 0) j += LL; else if (j >= LL) j -= LL;
        s[u] = xc[j];
    }
    __syncthreads();

    float* dst = g_XPK + ((size_t)b * CKD + (size_t)c * KW) * MP + m0;
    const int v0 = threadIdx.x * 4;      // one float4 per thread per tap
    if (m0 + v0 < MP) {
        #pragma unroll
        for (int k = 0; k < KW; k++) {
            float4 w = make_float4(s[3 * v0 + k],      s[3 * (v0 + 1) + k],
                                   s[3 * (v0 + 2) + k], s[3 * (v0 + 3) + k]);
            *(float4*)(dst + (size_t)k * MP + v0) = w;
        }
    }
}

// ---------------------------------------------------------------------------
// FUSED kernel: one block = 128 windows of one batch. Occupancy 3 target
// (85 regs/thread) so all 344 tiles are resident -> no wave-quantization tail.
// Phase 1 (GEMM1): H[o,p] = relu(sum_ck W1[o,ck]*XPK[b,ck,p] + b1[o]) -> smem,
//   plain pair layout Hs[o][pr]. A staged plain, duplicated in registers;
//   B pair-pairs {2tx,2tx+1} via one contiguous ulonglong2 LDS.
// Phase 2 (GEMM2): 32 window-groups (4 windows) x 8 channels; one WARP = one
//   channel. W2 per-cg tile = straight conflict-free float4 copy from g_W2P.
//   Full K=64 staged at once -> 2 barriers per cg. Taps via 2 LDS.128
//   broadcasts, dup in regs. H pairs one contiguous ulonglong2 per lane.
//   Fold in registers; ALIGNED exclusive-ownership store: pass fold[0..2]
//   down + fold[15] up -> owned l = 3pw0..3pw0+11 (4-aligned) -> 3x STG.128.
//   Atomics only at warp/block edges.
// 48KB static smem: Hs 32KB + union(Asf 4KB + Bs 8KB | W2sf 16KB).
// ---------------------------------------------------------------------------
#define F_TN 128                 // windows per block (64 pairs)
#define F_KC 16                  // phase-1 K chunk
#define F_CG 8                   // phase-2 channels per group (one per warp)

__global__ void __launch_bounds__(256, 3) k_fused(const float* __restrict__ b1,
                                                  const float* __restrict__ b2,
                                                  float* __restrict__ out) {
    __shared__ __align__(16) u64 Hs[IC][64];   // 32KB: H pairs, plain: Hs[o][pr]
    __shared__ __align__(16) u64 Sbuf[2048];   // 16KB union
    float (*Asf)[IC]  = (float(*)[IC])Sbuf;          // phase-1 W1T chunk floats: 4KB
    u64   (*Bs64)[64] = (u64(*)[64])(Sbuf + 512);    // phase-1 patch pairs: 8KB
    float (*W2sf)[64] = (float(*)[64])Sbuf;          // phase-2 W2 tile: [jj][ch*8+k] 16KB

    const int b   = blockIdx.y;
    const int p0  = blockIdx.x * F_TN;
    const int tid = threadIdx.x;

    // ===================== Phase 1: GEMM1 -> smem H =====================
    {
        const int ty = tid >> 5;         // 0..7 : rows o = ty*8 .. ty*8+7 (warp idx)
        const int tx = tid & 31;         // pair lane: pairs 2tx, 2tx+1
        const int fr = tid >> 4;         // fill row 0..15
        const int fc = tid & 15;         // fill col group

        u64 acc[8][2];                   // [row][pair 2tx / 2tx+1]
        #pragma unroll
        for (int i = 0; i < 8; i++) { acc[i][0] = 0ull; acc[i][1] = 0ull; }

        const float* xpkBase = g_XPK + (size_t)b * CKD * MP + p0 + fc * 8;

        // software-pipelined prefetch
        float4 aPre, bPre0, bPre1;
        aPre  = *(const float4*)(g_W1T + fr * IC + fc * 4);
        bPre0 = *(const float4*)(xpkBase + (size_t)fr * MP);
        bPre1 = *(const float4*)(xpkBase + (size_t)fr * MP + 4);

        for (int kc0 = 0; kc0 < CKD; kc0 += F_KC) {
            // commit prefetched chunk
            {
                *(float4*)&Asf[fr][fc * 4] = aPre;
                float* br = (float*)&Bs64[fr][0] + fc * 8;
                *(float4*)br       = bPre0;
                *(float4*)(br + 4) = bPre1;
            }
            __syncthreads();

            // issue next chunk's global loads early
            const int kn = kc0 + F_KC;
            if (kn < CKD) {
                aPre  = *(const float4*)(g_W1T + (kn + fr) * IC + fc * 4);
                bPre0 = *(const float4*)(xpkBase + (size_t)(kn + fr) * MP);
                bPre1 = *(const float4*)(xpkBase + (size_t)(kn + fr) * MP + 4);
            }

            #pragma unroll
            for (int kk = 0; kk < F_KC; kk++) {
                // A: 8 floats via 2 LDS.128 full-warp broadcasts, dup in regs
                float4 af0 = *(const float4*)&Asf[kk][ty * 8];
                float4 af1 = *(const float4*)&Asf[kk][ty * 8 + 4];
                u64 a[8] = { pack2(af0.x, af0.x), pack2(af0.y, af0.y),
                             pack2(af0.z, af0.z), pack2(af0.w, af0.w),
                             pack2(af1.x, af1.x), pack2(af1.y, af1.y),
                             pack2(af1.z, af1.z), pack2(af1.w, af1.w) };
                // B: adjacent pair-pair via one contiguous ulonglong2 LDS
                ulonglong2 bp = *(const ulonglong2*)&Bs64[kk][2 * tx];
                #pragma unroll
                for (int i = 0; i < 8; i++) {
                    ffma2(acc[i][0], a[i], bp.x);
                    ffma2(acc[i][1], a[i], bp.y);
                }
            }
            __syncthreads();
        }

        // epilogue: +b1, relu, one STS.128 per row (pairs 2tx, 2tx+1)
        float bias[8];
        #pragma unroll
        for (int i = 0; i < 8; i++) bias[i] = __ldg(b1 + ty * 8 + i);

        #pragma unroll
        for (int i = 0; i < 8; i++) {
            float lo0, hi0, lo1, hi1;
            unpack2(acc[i][0], lo0, hi0);
            unpack2(acc[i][1], lo1, hi1);
            ulonglong2 v;
            v.x = pack2(fmaxf(lo0 + bias[i], 0.f), fmaxf(hi0 + bias[i], 0.f));
            v.y = pack2(fmaxf(lo1 + bias[i], 0.f), fmaxf(hi1 + bias[i], 0.f));
            *(ulonglong2*)&Hs[ty * 8 + i][2 * tx] = v;
        }
    }

    // ===================== Phase 2: GEMM2 + fold + stores =====================
    const int txw = tid & 31;            // window group: 4 consecutive windows
    const int tcc = tid >> 5;            // channel within group = warp id, 0..7
    const int pw0 = p0 + txw * 4;

    for (int cg = 0; cg < CC / F_CG; cg++) {
        const int c = cg * F_CG + tcc;

        __syncthreads();                 // prior readers of W2sf/Asf/Bs done
        // W2 tile: straight conflict-free float4 copy (prepacked by k_prep_weights)
        {
            const float4* src = (const float4*)(g_W2P + cg * (IC * 64));
            float4* dst = (float4*)&W2sf[0][0];
            #pragma unroll
            for (int i = 0; i < 4; i++) dst[tid + 256 * i] = src[tid + 256 * i];
        }
        __syncthreads();

        u64 acc[KW][2];                  // [tap][window-pair]
        #pragma unroll
        for (int k = 0; k < KW; k++) { acc[k][0] = 0ull; acc[k][1] = 0ull; }

        #pragma unroll 8
        for (int jj = 0; jj < IC; jj++) {
            // W2 taps: 2x LDS.128 full-warp broadcasts, duplicate in regs
            float4 wf0 = *(const float4*)&W2sf[jj][tcc * 8];
            float4 wf1 = *(const float4*)&W2sf[jj][tcc * 8 + 4];
            u64 w[KW] = { pack2(wf0.x, wf0.x), pack2(wf0.y, wf0.y),
                          pack2(wf0.z, wf0.z), pack2(wf0.w, wf0.w),
                          pack2(wf1.x, wf1.x), pack2(wf1.y, wf1.y),
                          pack2(wf1.z, wf1.z) };
            // H pairs {2txw, 2txw+1}: one contiguous ulonglong2 per lane
            ulonglong2 hq = *(const ulonglong2*)&Hs[jj][2 * txw];
            #pragma unroll
            for (int k = 0; k < KW; k++) {
                ffma2(acc[k][0], w[k], hq.x);
                ffma2(acc[k][1], w[k], hq.y);
            }
        }

        // in-register fold: window jj tap k -> fold[3*jj + k]; l(i) = 3*pw0 + i - 3
        float fold[3 * 4 + KW - 3];      // 16
        #pragma unroll
        for (int i = 0; i < 16; i++) fold[i] = 0.f;

        float b2v[KW];
        #pragma unroll
        for (int k = 0; k < KW; k++) b2v[k] = __ldg(b2 + c * KW + k);

        #pragma unroll
        for (int jj = 0; jj < 4; jj++) {
            if (pw0 + jj < PP) {
                #pragma unroll
                for (int k = 0; k < KW; k++) {
                    float lo, hi; unpack2(acc[k][jj >> 1], lo, hi);
                    fold[3 * jj + k] += ((jj & 1) ? hi : lo) + b2v[k];
                }
            }
        }

        // Aligned ownership exchange (warp = one channel, lanes = windows):
        //   fold[0..2] -> lane-1 (adds into its fold[12..14])
        //   fold[15]   -> lane+1 (adds into its fold[3])
        // Owned exclusive region: fold[3..14] -> l = 3pw0 .. 3pw0+11 (mod 4 == 0).
        float d0 = __shfl_down_sync(0xffffffffu, fold[0], 1);
        float d1 = __shfl_down_sync(0xffffffffu, fold[1], 1);
        float d2 = __shfl_down_sync(0xffffffffu, fold[2], 1);
        float u3 = __shfl_up_sync(0xffffffffu, fold[15], 1);
        if (txw < 31) { fold[12] += d0; fold[13] += d1; fold[14] += d2; }
        if (txw > 0)  { fold[3]  += u3; }

        float* outc = out + ((size_t)b * CC + c) * LL;
        const int fbase = 3 * pw0;       // == l of fold[3]

        if (txw == 0) {
            // left edge: fold[0..3] shared with previous block -> atomic
            #pragma unroll
            for (int i = 0; i < 4; i++) {
                int l = fbase + i - 3;
                if (l >= 0 && l < LL) atomicAdd(outc + l, fold[i]);
            }
            #pragma unroll
            for (int i = 4; i < 15; i++) {      // exclusive, scalar (1/32 lanes)
                int l = fbase + i - 3;
                if (l < LL) outc[l] = fold[i];
            }
        } else if (txw == 31) {
            // exclusive fold[3..11], scalar (1/32 lanes)
            #pragma unroll
            for (int i = 3; i < 12; i++) {
                int l = fbase + i - 3;
                if (l < LL) outc[l] = fold[i];
            }
            // right edge: fold[12..15] shared with next block -> atomic
            #pragma unroll
            for (int i = 12; i < 16; i++) {
                int l = fbase + i - 3;
                if (l < LL) atomicAdd(outc + l, fold[i]);
            }
        } else {
            // bulk lanes: 3 aligned STG.128 (l and LL both mult of 4 -> no straddle)
            if (fbase < LL)
                *(float4*)(outc + fbase)     = make_float4(fold[3], fold[4], fold[5], fold[6]);
            if (fbase + 4 < LL)
                *(float4*)(outc + fbase + 4) = make_float4(fold[7], fold[8], fold[9], fold[10]);
            if (fbase + 8 < LL)
                *(float4*)(outc + fbase + 8) = make_float4(fold[11], fold[12], fold[13], fold[14]);
        }
    }
}

// ---------------------------------------------------------------------------
// Launch: memset -> prep weights (merged) -> de-interleave x -> fused kernel
// (default stream, graph-capturable, no allocations)
// ---------------------------------------------------------------------------
extern "C" void kernel_launch(void* const* d_in, const int* in_sizes, int n_in,
                              void* d_out, int out_size) {
    const float* x  = (const float*)d_in[0];
    const float* W1 = (const float*)d_in[1];
    const float* b1 = (const float*)d_in[2];
    const float* W2 = (const float*)d_in[3];
    const float* b2 = (const float*)d_in[4];
    float* out = (float*)d_out;

    cudaMemsetAsync(d_out, 0, (size_t)out_size * sizeof(float), 0);
    k_prep_weights<<<(W1T_N + W2P_N + 255) / 256, 256>>>(W1, W2);
    k_deinterleave<<<dim3((MP + SEG - 1) / SEG, CC, BB), 256>>>(x);
    k_fused<<<dim3((PP + F_TN - 1) / F_TN, BB), 256>>>(b1, b2, out);
}